// round 8
// baseline (speedup 1.0000x reference)
#include <cuda_runtime.h>
#include <cstdint>

#define DFEAT 48
#define NCG   12                       // float4 column-groups per row (48/4)
#define CHUNK 512                      // edges per chunk
#define NWALK 32                       // row-walkers per column-group
#define WALKR (CHUNK / NWALK)          // 16 rows per walker
#define MAIN_THREADS (NCG * NWALK)     // 384

#define TILE_BYTES   (CHUNK * DFEAT * 4)            // 98304 per buffer
#define SMEM_FT(b)   ((b) * TILE_BYTES)             // 2 tiles
#define SMEM_W_OFF   (2 * TILE_BYTES)               // w_s[2][CHUNK]
#define SMEM_S_OFF   (SMEM_W_OFF + 2 * CHUNK * 4)   // s_s[2][CHUNK]
#define SMEM_MB_OFF  (SMEM_S_OFF + 2 * CHUNK * 4)   // mbar[2]
#define SMEM_TOTAL   (SMEM_MB_OFF + 32)

// Per-node softmax denominators (N = 50000 here; padded)
__device__ float g_denom[65536];

// Edge-parallel denom accumulation: each thread takes 4 consecutive edges
// (float4/int4 loads), aggregates same-sid runs locally, flushes boundaries.
__global__ void k_exp(const float* __restrict__ a,
                      const int* __restrict__ seg, int E) {
    int t = blockIdx.x * blockDim.x + threadIdx.x;
    int e0 = t * 4;
    if (e0 >= E) return;

    if (e0 + 4 <= E) {
        float4 av = *(const float4*)(a + e0);
        int4   sv = *(const int4*)(seg + e0);
        float acc = __expf(av.x);
        int   cur = sv.x;
        if (sv.y != cur) { atomicAdd(&g_denom[cur], acc); acc = 0.0f; cur = sv.y; }
        acc += __expf(av.y);
        if (sv.z != cur) { atomicAdd(&g_denom[cur], acc); acc = 0.0f; cur = sv.z; }
        acc += __expf(av.z);
        if (sv.w != cur) { atomicAdd(&g_denom[cur], acc); acc = 0.0f; cur = sv.w; }
        acc += __expf(av.w);
        atomicAdd(&g_denom[cur], acc);
    } else {
        for (int e = e0; e < E; e++)
            atomicAdd(&g_denom[seg[e]], __expf(a[e]));
    }
}

__device__ __forceinline__ uint32_t smem_u32(const void* p) {
    return (uint32_t)__cvta_generic_to_shared(p);
}
__device__ __forceinline__ void mbar_init(uint32_t mbar, uint32_t count) {
    asm volatile("mbarrier.init.shared.b64 [%0], %1;" :: "r"(mbar), "r"(count) : "memory");
}
__device__ __forceinline__ void mbar_expect_tx(uint32_t mbar, uint32_t bytes) {
    asm volatile("mbarrier.arrive.expect_tx.shared.b64 _, [%0], %1;"
                 :: "r"(mbar), "r"(bytes) : "memory");
}
__device__ __forceinline__ void bulk_g2s(uint32_t dst_smem, const void* src_gmem,
                                         uint32_t bytes, uint32_t mbar) {
    asm volatile(
        "cp.async.bulk.shared::cta.global.mbarrier::complete_tx::bytes "
        "[%0], [%1], %2, [%3];"
        :: "r"(dst_smem), "l"(src_gmem), "r"(bytes), "r"(mbar) : "memory");
}
__device__ __forceinline__ void mbar_wait(uint32_t mbar, uint32_t parity) {
    asm volatile(
        "{\n\t"
        ".reg .pred P;\n\t"
        "W%=:\n\t"
        "mbarrier.try_wait.parity.shared::cta.b64 P, [%0], %1;\n\t"
        "@!P bra W%=;\n\t"
        "}"
        :: "r"(mbar), "r"(parity) : "memory");
}

__device__ __forceinline__ void flush4(float* __restrict__ out,
                                       int node, int cg, float4 acc) {
    float* p = out + (size_t)node * DFEAT + cg * 4;
    atomicAdd(p + 0, acc.x);
    atomicAdd(p + 1, acc.y);
    atomicAdd(p + 2, acc.z);
    atomicAdd(p + 3, acc.w);
}

// Persistent main pass: one block per SM, double-buffered TMA pipeline over
// contiguous 512-edge chunks. While computing buf, the TMA for the next chunk
// streams into buf^1 — DRAM never idles. Compute: 12 float4-column-groups x
// 32 row-walkers from smem; atomicAdd flush only at segment boundaries.
__global__ void __launch_bounds__(MAIN_THREADS, 1)
k_main(const float* __restrict__ a,
       const float* __restrict__ ft,
       const int* __restrict__ seg,
       float* __restrict__ out, int E) {
    extern __shared__ __align__(128) char smem[];
    float* w_all = (float*)(smem + SMEM_W_OFF);
    int*   s_all = (int*)(smem + SMEM_S_OFF);

    int tid = threadIdx.x;
    int nchunks = (E + CHUNK - 1) / CHUNK;
    int per = (nchunks + gridDim.x - 1) / gridDim.x;
    int c0 = blockIdx.x * per;
    int c1 = min(c0 + per, nchunks);
    if (c0 >= c1) return;

    uint32_t mb0 = smem_u32(smem + SMEM_MB_OFF);
    if (tid == 0) { mbar_init(mb0, 1); mbar_init(mb0 + 8, 1); }
    __syncthreads();

    // ---- stage helper (inlined twice): issue TMA + weights for chunk c into buffer b
    auto stage = [&](int c, int b) -> bool {
        int base = c * CHUNK;
        bool full = (base + CHUNK <= E);
        if (full && tid == 0) {
            uint32_t mb = mb0 + b * 8;
            mbar_expect_tx(mb, TILE_BYTES);
            bulk_g2s(smem_u32(smem + SMEM_FT(b)), ft + (size_t)base * DFEAT,
                     TILE_BYTES, mb);
        }
        float* w_s = w_all + b * CHUNK;
        int*   s_s = s_all + b * CHUNK;
        for (int i = tid; i < CHUNK; i += MAIN_THREADS) {
            int e = base + i;
            if (e < E) {
                int sid = seg[e];
                w_s[i] = __fdividef(__expf(a[e]), g_denom[sid]);
                s_s[i] = sid;
            } else {
                w_s[i] = 0.0f;
                s_s[i] = -1;
            }
        }
        if (!full) {
            const float4* ft4 = (const float4*)ft;
            float4* s_ft = (float4*)(smem + SMEM_FT(b));
            for (int i = tid; i < CHUNK * NCG; i += MAIN_THREADS) {
                int row = base + i / NCG;
                s_ft[i] = (row < E) ? ft4[(size_t)row * NCG + (i % NCG)]
                                    : make_float4(0.f, 0.f, 0.f, 0.f);
            }
        }
        return full;
    };

    int cg = tid % NCG;            // float4 column group (0..11)
    int y  = tid / NCG;            // walker id (0..31)
    int j0 = y * WALKR;

    // Prologue: stage first chunk into buf 0
    bool used_tma[2];
    used_tma[0] = stage(c0, 0);
    used_tma[1] = false;
    __syncthreads();               // weights visible before first compute

    int ph0 = 0, ph1 = 0;
    int buf = 0;

    for (int c = c0; c < c1; c++) {
        if (c + 1 < c1) used_tma[buf ^ 1] = stage(c + 1, buf ^ 1);

        if (used_tma[buf]) {
            if (buf == 0) { mbar_wait(mb0, ph0);     ph0 ^= 1; }
            else          { mbar_wait(mb0 + 8, ph1); ph1 ^= 1; }
        }

        const float4* s_ft = (const float4*)(smem + SMEM_FT(buf));
        const float*  w_s  = w_all + buf * CHUNK;
        const int*    s_s  = s_all + buf * CHUNK;

        int    cur = s_s[j0];
        float4 acc = make_float4(0.f, 0.f, 0.f, 0.f);

        #pragma unroll
        for (int k = 0; k < WALKR; k++) {
            int j = j0 + k;
            int    sid = s_s[j];
            float  w   = w_s[j];
            float4 v   = s_ft[j * NCG + cg];
            if (sid != cur) {
                if (cur >= 0) flush4(out, cur, cg, acc);
                acc = make_float4(0.f, 0.f, 0.f, 0.f);
                cur = sid;
            }
            acc.x += w * v.x;
            acc.y += w * v.y;
            acc.z += w * v.z;
            acc.w += w * v.w;
        }
        if (cur >= 0) flush4(out, cur, cg, acc);

        __syncthreads();           // all reads of buf done before it is refilled
        buf ^= 1;
    }
}

extern "C" void kernel_launch(void* const* d_in, const int* in_sizes, int n_in,
                              void* d_out, int out_size) {
    const float* a   = (const float*)d_in[0];
    const float* ft  = (const float*)d_in[1];
    const int*   seg = (const int*)d_in[2];
    float* out = (float*)d_out;

    int E = in_sizes[0];

    // Output accumulated via atomics -> zero it (harness poisons to 0xAA).
    cudaMemsetAsync(out, 0, (size_t)out_size * sizeof(float));

    // Zero denominators directly on the device symbol (no kernel launch).
    void* denom_ptr = nullptr;
    cudaGetSymbolAddress(&denom_ptr, g_denom);
    cudaMemsetAsync(denom_ptr, 0, sizeof(g_denom));

    int e4 = (E + 3) / 4;
    k_exp<<<(e4 + 255) / 256, 256>>>(a, seg, E);

    int sm_count = 148;
    cudaDeviceGetAttribute(&sm_count, cudaDevAttrMultiProcessorCount, 0);

    cudaFuncSetAttribute(k_main, cudaFuncAttributeMaxDynamicSharedMemorySize,
                         SMEM_TOTAL);
    k_main<<<sm_count, MAIN_THREADS, SMEM_TOTAL>>>(a, ft, seg, out, E);
}

// round 9
// speedup vs baseline: 1.0285x; 1.0285x over previous
#include <cuda_runtime.h>
#include <cstdint>

#define DFEAT 48
#define NCG   12                       // float4 column-groups per row (48/4)
#define CHUNK 512                      // edges per block in k_main
#define NWALK 32                       // row-walkers per column-group
#define WALKR (CHUNK / NWALK)          // 16 rows per walker
#define MAIN_THREADS (NCG * NWALK)     // 384

// Per-node softmax denominators (N = 50000 here; padded)
__device__ float g_denom[65536];

// Vectorized global reduction: one instruction instead of 4 scalar REDs.
__device__ __forceinline__ void red_add_v4(float* p, float4 v) {
    asm volatile("red.global.add.v4.f32 [%0], {%1, %2, %3, %4};"
                 :: "l"(p), "f"(v.x), "f"(v.y), "f"(v.z), "f"(v.w) : "memory");
}

// Main pass: block = 512 contiguous edges. Stage threads 0..127 each take 4
// consecutive edges (float4/int4 loads), compute UNNORMALIZED weights exp(a),
// write them to smem, and fuse the denominator accumulation (run-aggregated
// atomics on sorted sids). Then 12 float4-column-groups x 32 row-walkers each
// sweep 16 consecutive rows with LDG.128 and a running float4 segment
// accumulator; flush via one red.v4 only at segment boundaries.
__global__ void __launch_bounds__(MAIN_THREADS, 4)
k_main(const float* __restrict__ a,
       const float* __restrict__ ft,
       const int* __restrict__ seg,
       float* __restrict__ out, int E) {
    __shared__ float w_s[CHUNK];
    __shared__ int   s_s[CHUNK];

    int base = blockIdx.x * CHUNK;
    int tid  = threadIdx.x;

    // ---- Stage: weights + fused denom accumulation (threads 0..127) ----
    if (tid < CHUNK / 4) {
        int e0 = base + tid * 4;
        if (e0 + 4 <= E) {
            float4 av = *(const float4*)(a + e0);
            int4   sv = *(const int4*)(seg + e0);
            float ex0 = __expf(av.x), ex1 = __expf(av.y);
            float ex2 = __expf(av.z), ex3 = __expf(av.w);
            int j = tid * 4;
            w_s[j]     = ex0; s_s[j]     = sv.x;
            w_s[j + 1] = ex1; s_s[j + 1] = sv.y;
            w_s[j + 2] = ex2; s_s[j + 2] = sv.z;
            w_s[j + 3] = ex3; s_s[j + 3] = sv.w;
            // run-aggregated denom atomics (sids sorted)
            float acc = ex0; int cur = sv.x;
            if (sv.y != cur) { atomicAdd(&g_denom[cur], acc); acc = 0.0f; cur = sv.y; }
            acc += ex1;
            if (sv.z != cur) { atomicAdd(&g_denom[cur], acc); acc = 0.0f; cur = sv.z; }
            acc += ex2;
            if (sv.w != cur) { atomicAdd(&g_denom[cur], acc); acc = 0.0f; cur = sv.w; }
            acc += ex3;
            atomicAdd(&g_denom[cur], acc);
        } else {
            for (int k = 0; k < 4; k++) {
                int e = e0 + k, j = tid * 4 + k;
                if (e < E) {
                    float ex = __expf(a[e]);
                    int sid = seg[e];
                    w_s[j] = ex; s_s[j] = sid;
                    atomicAdd(&g_denom[sid], ex);
                } else {
                    w_s[j] = 0.0f; s_s[j] = -1;
                }
            }
        }
    }
    __syncthreads();

    int cg = tid % NCG;            // float4 column group (0..11)
    int y  = tid / NCG;            // walker id (0..31)
    int j0 = y * WALKR;

    const float4* ft4 = (const float4*)ft;

    int    cur = s_s[j0];
    float4 acc = make_float4(0.f, 0.f, 0.f, 0.f);

    if (base + CHUNK <= E) {
        // fast path: all rows valid
        #pragma unroll
        for (int k = 0; k < WALKR; k++) {
            int j = j0 + k;
            int    sid = s_s[j];
            float  w   = w_s[j];
            float4 v   = ft4[(size_t)(base + j) * NCG + cg];
            if (sid != cur) {
                red_add_v4(out + (size_t)cur * DFEAT + cg * 4, acc);
                acc = make_float4(0.f, 0.f, 0.f, 0.f);
                cur = sid;
            }
            acc.x += w * v.x;
            acc.y += w * v.y;
            acc.z += w * v.z;
            acc.w += w * v.w;
        }
        red_add_v4(out + (size_t)cur * DFEAT + cg * 4, acc);
    } else {
        for (int k = 0; k < WALKR; k++) {
            int j = j0 + k;
            int row = base + j;
            int   sid = s_s[j];
            float w   = w_s[j];
            float4 v = (row < E) ? ft4[(size_t)row * NCG + cg]
                                 : make_float4(0.f, 0.f, 0.f, 0.f);
            if (sid != cur) {
                if (cur >= 0) red_add_v4(out + (size_t)cur * DFEAT + cg * 4, acc);
                acc = make_float4(0.f, 0.f, 0.f, 0.f);
                cur = sid;
            }
            acc.x += w * v.x;
            acc.y += w * v.y;
            acc.z += w * v.z;
            acc.w += w * v.w;
        }
        if (cur >= 0) red_add_v4(out + (size_t)cur * DFEAT + cg * 4, acc);
    }
}

// Deferred normalization: out[n][:] *= 1/denom[n]. out is L2-resident here.
__global__ void k_norm(float* __restrict__ out, int N) {
    int t = blockIdx.x * blockDim.x + threadIdx.x;
    int node = t / NCG;
    int cg   = t % NCG;
    if (node >= N) return;
    float d = g_denom[node];
    float inv = (d > 0.0f) ? __frcp_rn(d) : 0.0f;
    float4* p = (float4*)(out + (size_t)node * DFEAT) + cg;
    float4 v = *p;
    v.x *= inv; v.y *= inv; v.z *= inv; v.w *= inv;
    *p = v;
}

extern "C" void kernel_launch(void* const* d_in, const int* in_sizes, int n_in,
                              void* d_out, int out_size) {
    const float* a   = (const float*)d_in[0];
    const float* ft  = (const float*)d_in[1];
    const int*   seg = (const int*)d_in[2];
    float* out = (float*)d_out;

    int E = in_sizes[0];
    int N = out_size / DFEAT;

    // Output accumulated via atomics -> zero it (harness poisons to 0xAA).
    cudaMemsetAsync(out, 0, (size_t)out_size * sizeof(float));

    // Zero denominators directly on the device symbol (no kernel launch).
    void* denom_ptr = nullptr;
    cudaGetSymbolAddress(&denom_ptr, g_denom);
    cudaMemsetAsync(denom_ptr, 0, sizeof(g_denom));

    int mb = (E + CHUNK - 1) / CHUNK;
    k_main<<<mb, MAIN_THREADS>>>(a, ft, seg, out, E);

    int nt = N * NCG;
    k_norm<<<(nt + 255) / 256, 256>>>(out, N);
}

// round 10
// speedup vs baseline: 1.2277x; 1.1937x over previous
#include <cuda_runtime.h>
#include <cstdint>

#define DFEAT 48
#define NCG   12                       // float4 column-groups per row (48/4)
#define CHUNK 256                      // edges per block in k_main
#define NWALK 32                       // row-walkers per column-group
#define WALKR (CHUNK / NWALK)          // 8 rows per walker
#define MAIN_THREADS (NCG * NWALK)     // 384

#define FT_TILE_BYTES (CHUNK * DFEAT * 4)          // 49152 (48KB)
#define SMEM_W_OFF    FT_TILE_BYTES                // w_s: CHUNK floats
#define SMEM_S_OFF    (FT_TILE_BYTES + CHUNK * 4)  // s_s: CHUNK ints
#define SMEM_MBAR_OFF (FT_TILE_BYTES + CHUNK * 8)  // mbarrier (8B)
#define SMEM_TOTAL    (SMEM_MBAR_OFF + 16)

// Per-node softmax denominators (N = 50000 here; padded)
__device__ float g_denom[65536];

// Edge-parallel denom accumulation: each thread takes 4 consecutive edges
// (float4/int4 loads), aggregates same-sid runs locally, flushes boundaries.
__global__ void k_exp(const float* __restrict__ a,
                      const int* __restrict__ seg, int E) {
    int t = blockIdx.x * blockDim.x + threadIdx.x;
    int e0 = t * 4;
    if (e0 >= E) return;

    if (e0 + 4 <= E) {
        float4 av = *(const float4*)(a + e0);
        int4   sv = *(const int4*)(seg + e0);
        float acc = __expf(av.x);
        int   cur = sv.x;
        if (sv.y != cur) { atomicAdd(&g_denom[cur], acc); acc = 0.0f; cur = sv.y; }
        acc += __expf(av.y);
        if (sv.z != cur) { atomicAdd(&g_denom[cur], acc); acc = 0.0f; cur = sv.z; }
        acc += __expf(av.z);
        if (sv.w != cur) { atomicAdd(&g_denom[cur], acc); acc = 0.0f; cur = sv.w; }
        acc += __expf(av.w);
        atomicAdd(&g_denom[cur], acc);
    } else {
        for (int e = e0; e < E; e++)
            atomicAdd(&g_denom[seg[e]], __expf(a[e]));
    }
}

__device__ __forceinline__ uint32_t smem_u32(const void* p) {
    return (uint32_t)__cvta_generic_to_shared(p);
}
__device__ __forceinline__ void mbar_init(uint32_t mbar, uint32_t count) {
    asm volatile("mbarrier.init.shared.b64 [%0], %1;" :: "r"(mbar), "r"(count) : "memory");
}
__device__ __forceinline__ void mbar_expect_tx(uint32_t mbar, uint32_t bytes) {
    asm volatile("mbarrier.arrive.expect_tx.shared.b64 _, [%0], %1;"
                 :: "r"(mbar), "r"(bytes) : "memory");
}
__device__ __forceinline__ void bulk_g2s(uint32_t dst_smem, const void* src_gmem,
                                         uint32_t bytes, uint32_t mbar) {
    asm volatile(
        "cp.async.bulk.shared::cta.global.mbarrier::complete_tx::bytes "
        "[%0], [%1], %2, [%3];"
        :: "r"(dst_smem), "l"(src_gmem), "r"(bytes), "r"(mbar) : "memory");
}
__device__ __forceinline__ void mbar_wait(uint32_t mbar, uint32_t parity) {
    asm volatile(
        "{\n\t"
        ".reg .pred P;\n\t"
        "W%=:\n\t"
        "mbarrier.try_wait.parity.shared::cta.b64 P, [%0], %1;\n\t"
        "@!P bra W%=;\n\t"
        "}"
        :: "r"(mbar), "r"(parity) : "memory");
}

// Vectorized global reduction: one instruction instead of 4 scalar REDs.
__device__ __forceinline__ void red_add_v4(float* p, float4 v) {
    asm volatile("red.global.add.v4.f32 [%0], {%1, %2, %3, %4};"
                 :: "l"(p), "f"(v.x), "f"(v.y), "f"(v.z), "f"(v.w) : "memory");
}

// Main pass: block = 256 contiguous edges, 48KB TMA tile -> 4 blocks/SM so
// TMA and compute phases of different blocks interleave and DRAM never
// idles. Weight staging overlaps the bulk copy. Compute: 12 float4-column-
// groups x 32 row-walkers from smem; red.v4 flush only at segment boundaries.
__global__ void __launch_bounds__(MAIN_THREADS, 4)
k_main(const float* __restrict__ a,
       const float* __restrict__ ft,
       const int* __restrict__ seg,
       float* __restrict__ out, int E) {
    extern __shared__ __align__(128) char smem[];
    float4* s_ft = (float4*)smem;
    float*  w_s  = (float*)(smem + SMEM_W_OFF);
    int*    s_s  = (int*)(smem + SMEM_S_OFF);
    uint32_t mbar = smem_u32(smem + SMEM_MBAR_OFF);

    int base = blockIdx.x * CHUNK;
    int tid  = threadIdx.x;
    bool full = (base + CHUNK <= E);

    if (tid == 0) mbar_init(mbar, 1);
    __syncthreads();

    if (full && tid == 0) {
        mbar_expect_tx(mbar, FT_TILE_BYTES);
        bulk_g2s(smem_u32(s_ft), ft + (size_t)base * DFEAT, FT_TILE_BYTES, mbar);
    }

    // Stage per-edge softmax weights (overlaps the TMA copy)
    if (tid < CHUNK) {
        int e = base + tid;
        if (e < E) {
            int sid = seg[e];
            w_s[tid] = __fdividef(__expf(a[e]), g_denom[sid]);
            s_s[tid] = sid;
        } else {
            w_s[tid] = 0.0f;
            s_s[tid] = -1;
        }
    }

    if (!full) {
        // Tail chunk: guarded per-thread loads into smem
        const float4* ft4 = (const float4*)ft;
        for (int i = tid; i < CHUNK * NCG; i += MAIN_THREADS) {
            int row = base + i / NCG;
            s_ft[i] = (row < E) ? ft4[(size_t)row * NCG + (i % NCG)]
                                : make_float4(0.f, 0.f, 0.f, 0.f);
        }
    }
    __syncthreads();
    if (full) mbar_wait(mbar, 0);

    int cg = tid % NCG;            // float4 column group (0..11)
    int y  = tid / NCG;            // walker id (0..31)
    int j0 = y * WALKR;

    int    cur = s_s[j0];
    float4 acc = make_float4(0.f, 0.f, 0.f, 0.f);

    #pragma unroll
    for (int k = 0; k < WALKR; k++) {
        int j = j0 + k;
        int    sid = s_s[j];
        float  w   = w_s[j];
        float4 v   = s_ft[j * NCG + cg];
        if (sid != cur) {
            if (cur >= 0) red_add_v4(out + (size_t)cur * DFEAT + cg * 4, acc);
            acc = make_float4(0.f, 0.f, 0.f, 0.f);
            cur = sid;
        }
        acc.x += w * v.x;
        acc.y += w * v.y;
        acc.z += w * v.z;
        acc.w += w * v.w;
    }
    if (cur >= 0) red_add_v4(out + (size_t)cur * DFEAT + cg * 4, acc);
}

extern "C" void kernel_launch(void* const* d_in, const int* in_sizes, int n_in,
                              void* d_out, int out_size) {
    const float* a   = (const float*)d_in[0];
    const float* ft  = (const float*)d_in[1];
    const int*   seg = (const int*)d_in[2];
    float* out = (float*)d_out;

    int E = in_sizes[0];

    // Output accumulated via atomics -> zero it (harness poisons to 0xAA).
    cudaMemsetAsync(out, 0, (size_t)out_size * sizeof(float));

    // Zero denominators directly on the device symbol (no kernel launch).
    void* denom_ptr = nullptr;
    cudaGetSymbolAddress(&denom_ptr, g_denom);
    cudaMemsetAsync(denom_ptr, 0, sizeof(g_denom));

    int e4 = (E + 3) / 4;
    k_exp<<<(e4 + 255) / 256, 256>>>(a, seg, E);

    cudaFuncSetAttribute(k_main, cudaFuncAttributeMaxDynamicSharedMemorySize,
                         SMEM_TOTAL);
    int mb = (E + CHUNK - 1) / CHUNK;
    k_main<<<mb, MAIN_THREADS, SMEM_TOTAL>>>(a, ft, seg, out, E);
}

// round 11
// speedup vs baseline: 1.2730x; 1.0369x over previous
#include <cuda_runtime.h>
#include <cstdint>

#define DFEAT 48
#define NCG   12                       // float4 column-groups per row (48/4)
#define CHUNK 256                      // edges per block in k_main
#define NWALK 32                       // row-walkers per column-group
#define WALKR (CHUNK / NWALK)          // 8 rows per walker
#define MAIN_THREADS (NCG * NWALK)     // 384

#define HALF_ROWS     (CHUNK / 2)                  // 128 rows per TMA half
#define HALF_BYTES    (HALF_ROWS * DFEAT * 4)      // 24576
#define FT_TILE_BYTES (CHUNK * DFEAT * 4)          // 49152 (48KB)
#define SMEM_W_OFF    FT_TILE_BYTES                // w_s: CHUNK floats
#define SMEM_S_OFF    (FT_TILE_BYTES + CHUNK * 4)  // s_s: CHUNK ints
#define SMEM_MBAR_OFF (FT_TILE_BYTES + CHUNK * 8)  // mbar[2]
#define SMEM_TOTAL    (SMEM_MBAR_OFF + 32)

// Per-node softmax denominators (N = 50000 here; padded)
__device__ float g_denom[65536];

// Edge-parallel denom accumulation (8 consecutive edges/thread, float4/int4
// loads, run-aggregated atomics on sorted sids) + fused grid-stride zeroing
// of the output buffer (must precede k_main's atomics).
__global__ void k_exp(const float* __restrict__ a,
                      const int* __restrict__ seg, int E,
                      float4* __restrict__ out4, int out_n4) {
    int t = blockIdx.x * blockDim.x + threadIdx.x;

    // Fused: zero the output (harness poisons it to 0xAA)
    int nthreads = gridDim.x * blockDim.x;
    for (int i = t; i < out_n4; i += nthreads)
        out4[i] = make_float4(0.f, 0.f, 0.f, 0.f);

    int e0 = t * 8;
    if (e0 >= E) return;

    if (e0 + 8 <= E) {
        float acc = 0.0f;
        int cur = -1;
        #pragma unroll
        for (int h = 0; h < 2; h++) {
            float4 av = *(const float4*)(a + e0 + h * 4);
            int4   sv = *(const int4*)(seg + e0 + h * 4);
            float ex[4] = {__expf(av.x), __expf(av.y), __expf(av.z), __expf(av.w)};
            int   sd[4] = {sv.x, sv.y, sv.z, sv.w};
            #pragma unroll
            for (int k = 0; k < 4; k++) {
                if (sd[k] != cur) {
                    if (cur >= 0) atomicAdd(&g_denom[cur], acc);
                    acc = 0.0f; cur = sd[k];
                }
                acc += ex[k];
            }
        }
        atomicAdd(&g_denom[cur], acc);
    } else {
        for (int e = e0; e < E; e++)
            atomicAdd(&g_denom[seg[e]], __expf(a[e]));
    }
}

__device__ __forceinline__ uint32_t smem_u32(const void* p) {
    return (uint32_t)__cvta_generic_to_shared(p);
}
__device__ __forceinline__ void mbar_init(uint32_t mbar, uint32_t count) {
    asm volatile("mbarrier.init.shared.b64 [%0], %1;" :: "r"(mbar), "r"(count) : "memory");
}
__device__ __forceinline__ void mbar_expect_tx(uint32_t mbar, uint32_t bytes) {
    asm volatile("mbarrier.arrive.expect_tx.shared.b64 _, [%0], %1;"
                 :: "r"(mbar), "r"(bytes) : "memory");
}
__device__ __forceinline__ void bulk_g2s(uint32_t dst_smem, const void* src_gmem,
                                         uint32_t bytes, uint32_t mbar) {
    asm volatile(
        "cp.async.bulk.shared::cta.global.mbarrier::complete_tx::bytes "
        "[%0], [%1], %2, [%3];"
        :: "r"(dst_smem), "l"(src_gmem), "r"(bytes), "r"(mbar) : "memory");
}
__device__ __forceinline__ void mbar_wait(uint32_t mbar, uint32_t parity) {
    asm volatile(
        "{\n\t"
        ".reg .pred P;\n\t"
        "W%=:\n\t"
        "mbarrier.try_wait.parity.shared::cta.b64 P, [%0], %1;\n\t"
        "@!P bra W%=;\n\t"
        "}"
        :: "r"(mbar), "r"(parity) : "memory");
}

// Vectorized global reduction: one instruction instead of 4 scalar REDs.
__device__ __forceinline__ void red_add_v4(float* p, float4 v) {
    asm volatile("red.global.add.v4.f32 [%0], {%1, %2, %3, %4};"
                 :: "l"(p), "f"(v.x), "f"(v.y), "f"(v.z), "f"(v.w) : "memory");
}

// Main pass: block = 256 contiguous edges. Tile split into two 24KB TMA
// copies with separate mbarriers: warps consuming rows 0-127 wait only on
// the first half, so compute starts as soon as half the tile lands. 4
// blocks/SM interleave TMA and compute phases so DRAM never idles.
// Compute: 12 float4-column-groups x 32 row-walkers from smem; red.v4 flush
// only at segment boundaries (seg is sorted).
__global__ void __launch_bounds__(MAIN_THREADS, 4)
k_main(const float* __restrict__ a,
       const float* __restrict__ ft,
       const int* __restrict__ seg,
       float* __restrict__ out, int E) {
    extern __shared__ __align__(128) char smem[];
    float4* s_ft = (float4*)smem;
    float*  w_s  = (float*)(smem + SMEM_W_OFF);
    int*    s_s  = (int*)(smem + SMEM_S_OFF);
    uint32_t mb0 = smem_u32(smem + SMEM_MBAR_OFF);

    int base = blockIdx.x * CHUNK;
    int tid  = threadIdx.x;
    bool full = (base + CHUNK <= E);

    if (tid == 0) { mbar_init(mb0, 1); mbar_init(mb0 + 8, 1); }
    __syncthreads();

    if (full && tid == 0) {
        mbar_expect_tx(mb0, HALF_BYTES);
        bulk_g2s(smem_u32(s_ft), ft + (size_t)base * DFEAT, HALF_BYTES, mb0);
        mbar_expect_tx(mb0 + 8, HALF_BYTES);
        bulk_g2s(smem_u32(s_ft) + HALF_BYTES,
                 ft + (size_t)(base + HALF_ROWS) * DFEAT, HALF_BYTES, mb0 + 8);
    }

    // Stage per-edge softmax weights (overlaps the TMA copies)
    if (tid < CHUNK) {
        int e = base + tid;
        if (e < E) {
            int sid = seg[e];
            w_s[tid] = __fdividef(__expf(a[e]), g_denom[sid]);
            s_s[tid] = sid;
        } else {
            w_s[tid] = 0.0f;
            s_s[tid] = -1;
        }
    }

    if (!full) {
        // Tail chunk: guarded per-thread loads into smem
        const float4* ft4 = (const float4*)ft;
        for (int i = tid; i < CHUNK * NCG; i += MAIN_THREADS) {
            int row = base + i / NCG;
            s_ft[i] = (row < E) ? ft4[(size_t)row * NCG + (i % NCG)]
                                : make_float4(0.f, 0.f, 0.f, 0.f);
        }
    }
    __syncthreads();

    int cg = tid % NCG;            // float4 column group (0..11)
    int y  = tid / NCG;            // walker id (0..31)
    int j0 = y * WALKR;

    // Warps consuming rows [0,128) wait on mb0; rows [128,256) on mb1.
    if (full) mbar_wait(j0 < HALF_ROWS ? mb0 : mb0 + 8, 0);

    int    cur = s_s[j0];
    float4 acc = make_float4(0.f, 0.f, 0.f, 0.f);

    #pragma unroll
    for (int k = 0; k < WALKR; k++) {
        int j = j0 + k;
        int    sid = s_s[j];
        float  w   = w_s[j];
        float4 v   = s_ft[j * NCG + cg];
        if (sid != cur) {
            if (cur >= 0) red_add_v4(out + (size_t)cur * DFEAT + cg * 4, acc);
            acc = make_float4(0.f, 0.f, 0.f, 0.f);
            cur = sid;
        }
        acc.x += w * v.x;
        acc.y += w * v.y;
        acc.z += w * v.z;
        acc.w += w * v.w;
    }
    if (cur >= 0) red_add_v4(out + (size_t)cur * DFEAT + cg * 4, acc);
}

extern "C" void kernel_launch(void* const* d_in, const int* in_sizes, int n_in,
                              void* d_out, int out_size) {
    const float* a   = (const float*)d_in[0];
    const float* ft  = (const float*)d_in[1];
    const int*   seg = (const int*)d_in[2];
    float* out = (float*)d_out;

    int E = in_sizes[0];

    // Zero denominators directly on the device symbol (no kernel launch).
    void* denom_ptr = nullptr;
    cudaGetSymbolAddress(&denom_ptr, g_denom);
    cudaMemsetAsync(denom_ptr, 0, sizeof(g_denom));

    // k_exp also zeroes the output buffer (fused).
    int e8 = (E + 7) / 8;
    k_exp<<<(e8 + 255) / 256, 256>>>(a, seg, E, (float4*)out, out_size / 4);

    cudaFuncSetAttribute(k_main, cudaFuncAttributeMaxDynamicSharedMemorySize,
                         SMEM_TOTAL);
    int mb = (E + CHUNK - 1) / CHUNK;
    k_main<<<mb, MAIN_THREADS, SMEM_TOTAL>>>(a, ft, seg, out, E);
}

// round 12
// speedup vs baseline: 1.3188x; 1.0360x over previous
#include <cuda_runtime.h>
#include <cstdint>

#define DFEAT 48
#define NCG   12                       // float4 column-groups per row (48/4)
#define CHUNK 256                      // edges per block in k_main
#define NWALK 32                       // row-walkers per column-group
#define WALKR (CHUNK / NWALK)          // 8 rows per walker
#define MAIN_THREADS (NCG * NWALK)     // 384

#define HALF_ROWS     (CHUNK / 2)                  // 128 rows per TMA half
#define HALF_BYTES    (HALF_ROWS * DFEAT * 4)      // 24576
#define FT_TILE_BYTES (CHUNK * DFEAT * 4)          // 49152 (48KB)
#define SMEM_W_OFF    FT_TILE_BYTES                // w_s: CHUNK floats
#define SMEM_S_OFF    (FT_TILE_BYTES + CHUNK * 4)  // s_s: CHUNK ints
#define SMEM_MBAR_OFF (FT_TILE_BYTES + CHUNK * 8)  // mbar[2]
#define SMEM_TOTAL    (SMEM_MBAR_OFF + 32)

// Per-node softmax denominators (N = 50000 here; padded)
__device__ float g_denom[65536];

// Edge-parallel denom accumulation (8 consecutive edges/thread, float4/int4
// loads, run-aggregated atomics on sorted sids) + fused grid-stride zeroing
// of the output buffer. Triggers PDL immediately so k_main's independent
// prologue (TMA issue + exp staging) overlaps this kernel.
__global__ void k_exp(const float* __restrict__ a,
                      const int* __restrict__ seg, int E,
                      float4* __restrict__ out4, int out_n4) {
#if __CUDA_ARCH__ >= 900
    cudaTriggerProgrammaticLaunchCompletion();
#endif
    int t = blockIdx.x * blockDim.x + threadIdx.x;

    // Fused: zero the output (harness poisons it to 0xAA)
    int nthreads = gridDim.x * blockDim.x;
    for (int i = t; i < out_n4; i += nthreads)
        out4[i] = make_float4(0.f, 0.f, 0.f, 0.f);

    int e0 = t * 8;
    if (e0 >= E) return;

    if (e0 + 8 <= E) {
        float acc = 0.0f;
        int cur = -1;
        #pragma unroll
        for (int h = 0; h < 2; h++) {
            float4 av = *(const float4*)(a + e0 + h * 4);
            int4   sv = *(const int4*)(seg + e0 + h * 4);
            float ex[4] = {__expf(av.x), __expf(av.y), __expf(av.z), __expf(av.w)};
            int   sd[4] = {sv.x, sv.y, sv.z, sv.w};
            #pragma unroll
            for (int k = 0; k < 4; k++) {
                if (sd[k] != cur) {
                    if (cur >= 0) atomicAdd(&g_denom[cur], acc);
                    acc = 0.0f; cur = sd[k];
                }
                acc += ex[k];
            }
        }
        atomicAdd(&g_denom[cur], acc);
    } else {
        for (int e = e0; e < E; e++)
            atomicAdd(&g_denom[seg[e]], __expf(a[e]));
    }
}

__device__ __forceinline__ uint32_t smem_u32(const void* p) {
    return (uint32_t)__cvta_generic_to_shared(p);
}
__device__ __forceinline__ void mbar_init(uint32_t mbar, uint32_t count) {
    asm volatile("mbarrier.init.shared.b64 [%0], %1;" :: "r"(mbar), "r"(count) : "memory");
}
__device__ __forceinline__ void mbar_expect_tx(uint32_t mbar, uint32_t bytes) {
    asm volatile("mbarrier.arrive.expect_tx.shared.b64 _, [%0], %1;"
                 :: "r"(mbar), "r"(bytes) : "memory");
}
__device__ __forceinline__ void bulk_g2s(uint32_t dst_smem, const void* src_gmem,
                                         uint32_t bytes, uint32_t mbar) {
    asm volatile(
        "cp.async.bulk.shared::cta.global.mbarrier::complete_tx::bytes "
        "[%0], [%1], %2, [%3];"
        :: "r"(dst_smem), "l"(src_gmem), "r"(bytes), "r"(mbar) : "memory");
}
__device__ __forceinline__ void mbar_wait(uint32_t mbar, uint32_t parity) {
    asm volatile(
        "{\n\t"
        ".reg .pred P;\n\t"
        "W%=:\n\t"
        "mbarrier.try_wait.parity.shared::cta.b64 P, [%0], %1;\n\t"
        "@!P bra W%=;\n\t"
        "}"
        :: "r"(mbar), "r"(parity) : "memory");
}

// Vectorized global reduction: one instruction instead of 4 scalar REDs.
__device__ __forceinline__ void red_add_v4(float* p, float4 v) {
    asm volatile("red.global.add.v4.f32 [%0], {%1, %2, %3, %4};"
                 :: "l"(p), "f"(v.x), "f"(v.y), "f"(v.z), "f"(v.w) : "memory");
}

// Main pass: block = 256 contiguous edges. Launched via PDL — TMA issue and
// exp/sid staging run before grid-dependency-sync (independent of k_exp);
// only the denom division waits. Tile split into two 24KB TMA copies with
// separate mbarriers; 4 blocks/SM interleave TMA and compute phases.
// Compute: 12 float4-column-groups x 32 row-walkers from smem; red.v4 flush
// only at segment boundaries (seg is sorted).
__global__ void __launch_bounds__(MAIN_THREADS, 4)
k_main(const float* __restrict__ a,
       const float* __restrict__ ft,
       const int* __restrict__ seg,
       float* __restrict__ out, int E) {
    extern __shared__ __align__(128) char smem[];
    float4* s_ft = (float4*)smem;
    float*  w_s  = (float*)(smem + SMEM_W_OFF);
    int*    s_s  = (int*)(smem + SMEM_S_OFF);
    uint32_t mb0 = smem_u32(smem + SMEM_MBAR_OFF);

    int base = blockIdx.x * CHUNK;
    int tid  = threadIdx.x;
    bool full = (base + CHUNK <= E);

    if (tid == 0) { mbar_init(mb0, 1); mbar_init(mb0 + 8, 1); }
    __syncthreads();

    if (full && tid == 0) {
        mbar_expect_tx(mb0, HALF_BYTES);
        bulk_g2s(smem_u32(s_ft), ft + (size_t)base * DFEAT, HALF_BYTES, mb0);
        mbar_expect_tx(mb0 + 8, HALF_BYTES);
        bulk_g2s(smem_u32(s_ft) + HALF_BYTES,
                 ft + (size_t)(base + HALF_ROWS) * DFEAT, HALF_BYTES, mb0 + 8);
    }

    // Stage exp(a) and sid (independent of k_exp's denominators)
    float ex = 0.0f;
    int   sid_t = -1;
    if (tid < CHUNK) {
        int e = base + tid;
        if (e < E) {
            sid_t = seg[e];
            ex = __expf(a[e]);
        }
        s_s[tid] = sid_t;
    }

    if (!full) {
        // Tail chunk: guarded per-thread loads into smem
        const float4* ft4 = (const float4*)ft;
        for (int i = tid; i < CHUNK * NCG; i += MAIN_THREADS) {
            int row = base + i / NCG;
            s_ft[i] = (row < E) ? ft4[(size_t)row * NCG + (i % NCG)]
                                : make_float4(0.f, 0.f, 0.f, 0.f);
        }
    }

#if __CUDA_ARCH__ >= 900
    cudaGridDependencySynchronize();   // k_exp (denom + out zero) complete
#endif

    if (tid < CHUNK)
        w_s[tid] = (sid_t >= 0) ? __fdividef(ex, g_denom[sid_t]) : 0.0f;

    __syncthreads();

    int cg = tid % NCG;            // float4 column group (0..11)
    int y  = tid / NCG;            // walker id (0..31)
    int j0 = y * WALKR;

    // Warps consuming rows [0,128) wait on mb0; rows [128,256) on mb1.
    if (full) mbar_wait(j0 < HALF_ROWS ? mb0 : mb0 + 8, 0);

    int    cur = s_s[j0];
    float4 acc = make_float4(0.f, 0.f, 0.f, 0.f);

    #pragma unroll
    for (int k = 0; k < WALKR; k++) {
        int j = j0 + k;
        int    sid = s_s[j];
        float  w   = w_s[j];
        float4 v   = s_ft[j * NCG + cg];
        if (sid != cur) {
            if (cur >= 0) red_add_v4(out + (size_t)cur * DFEAT + cg * 4, acc);
            acc = make_float4(0.f, 0.f, 0.f, 0.f);
            cur = sid;
        }
        acc.x += w * v.x;
        acc.y += w * v.y;
        acc.z += w * v.z;
        acc.w += w * v.w;
    }
    if (cur >= 0) red_add_v4(out + (size_t)cur * DFEAT + cg * 4, acc);
}

extern "C" void kernel_launch(void* const* d_in, const int* in_sizes, int n_in,
                              void* d_out, int out_size) {
    const float* a   = (const float*)d_in[0];
    const float* ft  = (const float*)d_in[1];
    const int*   seg = (const int*)d_in[2];
    float* out = (float*)d_out;

    int E = in_sizes[0];

    // Zero denominators directly on the device symbol (no kernel launch).
    void* denom_ptr = nullptr;
    cudaGetSymbolAddress(&denom_ptr, g_denom);
    cudaMemsetAsync(denom_ptr, 0, sizeof(g_denom));

    // k_exp also zeroes the output buffer (fused).
    int e8 = (E + 7) / 8;
    k_exp<<<(e8 + 255) / 256, 256>>>(a, seg, E, (float4*)out, out_size / 4);

    cudaFuncSetAttribute(k_main, cudaFuncAttributeMaxDynamicSharedMemorySize,
                         SMEM_TOTAL);
    int mb = (E + CHUNK - 1) / CHUNK;

    // PDL launch: k_main's prologue overlaps k_exp.
    cudaLaunchConfig_t cfg = {};
    cfg.gridDim = dim3(mb);
    cfg.blockDim = dim3(MAIN_THREADS);
    cfg.dynamicSmemBytes = SMEM_TOTAL;
    cudaLaunchAttribute attrs[1];
    attrs[0].id = cudaLaunchAttributeProgrammaticStreamSerialization;
    attrs[0].val.programmaticStreamSerializationAllowed = 1;
    cfg.attrs = attrs;
    cfg.numAttrs = 1;
    cudaLaunchKernelEx(&cfg, k_main, a, ft, seg, out, E);
}